// round 12
// baseline (speedup 1.0000x reference)
#include <cuda_runtime.h>
#include <cuda_fp16.h>
#include <math.h>

#define NMAX 50000
#define MMAX 800000
#define DD 256

// ---------------- scratch (static device globals; no allocation) ----------------
__device__ __align__(16) __half g_Q[(size_t)NMAX * DD];
__device__ __align__(16) __half g_K[(size_t)NMAX * DD];
__device__ __align__(16) __half g_V[(size_t)NMAX * DD];
__device__ __align__(16) __half g_agg[(size_t)NMAX * DD];  // relu'd messages (fp16)
__device__ __align__(16) __half g_WT[5 * 65536];           // weights fp16, [n][k]
__device__ __align__(16) float  g_att[(size_t)MMAX * 8];   // qk logits (CSR edge order)
__device__ int g_hist[NMAX];
__device__ int g_cursor[NMAX];
__device__ int g_rowoff[NMAX + 1];
__device__ int g_send_s[MMAX];
__device__ int g_bsum[64];
__device__ int g_maxbits;

__device__ __forceinline__ int f2ord(float f) {
    int b = __float_as_int(f);
    return b >= 0 ? b : (b ^ 0x7FFFFFFF);
}
__device__ __forceinline__ float ord2f(int b) {
    return __int_as_float(b >= 0 ? b : (b ^ 0x7FFFFFFF));
}

__device__ __forceinline__ void mma_f16(float* c, unsigned a0, unsigned a1,
                                        unsigned a2, unsigned a3,
                                        unsigned b0, unsigned b1) {
    asm volatile(
        "mma.sync.aligned.m16n8k16.row.col.f32.f16.f16.f32 "
        "{%0,%1,%2,%3}, {%4,%5,%6,%7}, {%8,%9}, {%0,%1,%2,%3};"
        : "+f"(c[0]), "+f"(c[1]), "+f"(c[2]), "+f"(c[3])
        : "r"(a0), "r"(a1), "r"(a2), "r"(a3), "r"(b0), "r"(b1));
}

__device__ __forceinline__ void ldsm_x4(unsigned& r0, unsigned& r1,
                                        unsigned& r2, unsigned& r3, const __half* p) {
    unsigned a = (unsigned)__cvta_generic_to_shared(p);
    asm volatile("ldmatrix.sync.aligned.m8n8.x4.shared.b16 {%0,%1,%2,%3}, [%4];"
                 : "=r"(r0), "=r"(r1), "=r"(r2), "=r"(r3) : "r"(a));
}

__device__ __forceinline__ void cp_async16(void* smem, const void* gmem) {
    unsigned sa = (unsigned)__cvta_generic_to_shared(smem);
    asm volatile("cp.async.cg.shared.global [%0], [%1], 16;" :: "r"(sa), "l"(gmem));
}
__device__ __forceinline__ void cp_async16_pred(void* smem, const void* gmem, bool p) {
    unsigned sa = (unsigned)__cvta_generic_to_shared(smem);
    int sz = p ? 16 : 0;
    asm volatile("cp.async.cg.shared.global [%0], [%1], 16, %2;"
                 :: "r"(sa), "l"(gmem), "r"(sz));
}
__device__ __forceinline__ void cp_commit() {
    asm volatile("cp.async.commit_group;");
}
template<int N>
__device__ __forceinline__ void cp_wait() {
    asm volatile("cp.async.wait_group %0;" :: "n"(N));
}

// ---------------- CSR build ----------------
__global__ void init_kernel(int n) {
    int i = blockIdx.x * blockDim.x + threadIdx.x;
    if (i < n) g_hist[i] = 0;
    if (i == 0) g_maxbits = 0x80000000;
}

__global__ void hist_kernel(const int* __restrict__ recv, int m) {
    int i = blockIdx.x * blockDim.x + threadIdx.x;
    if (i < m) atomicAdd(&g_hist[recv[i]], 1);
}

#define SCAN_NB 64
#define SCAN_NT 256

__global__ __launch_bounds__(SCAN_NT)
void scan_p1(int n) {
    __shared__ int sh[SCAN_NT];
    const int chunk = (n + SCAN_NB * SCAN_NT - 1) / (SCAN_NB * SCAN_NT);
    const int gid = blockIdx.x * SCAN_NT + threadIdx.x;
    const int base = gid * chunk;
    const int lim = min(base + chunk, n);
    int s = 0;
    for (int i = base; i < lim; ++i) s += g_hist[i];
    sh[threadIdx.x] = s;
    __syncthreads();
    for (int off = SCAN_NT / 2; off; off >>= 1) {
        if (threadIdx.x < off) sh[threadIdx.x] += sh[threadIdx.x + off];
        __syncthreads();
    }
    if (threadIdx.x == 0) g_bsum[blockIdx.x] = sh[0];
}

__global__ __launch_bounds__(SCAN_NB)
void scan_p2() {
    __shared__ int sh[SCAN_NB];
    const int t = threadIdx.x;
    int v = g_bsum[t];
    sh[t] = v;
    __syncthreads();
    for (int off = 1; off < SCAN_NB; off <<= 1) {
        int u = (t >= off) ? sh[t - off] : 0;
        __syncthreads();
        sh[t] += u;
        __syncthreads();
    }
    g_bsum[t] = sh[t] - v;
}

__global__ __launch_bounds__(SCAN_NT)
void scan_p3(int n, int m) {
    __shared__ int sh[SCAN_NT];
    const int chunk = (n + SCAN_NB * SCAN_NT - 1) / (SCAN_NB * SCAN_NT);
    const int gid = blockIdx.x * SCAN_NT + threadIdx.x;
    const int base = gid * chunk;
    const int lim = min(base + chunk, n);
    int s = 0;
    for (int i = base; i < lim; ++i) s += g_hist[i];
    sh[threadIdx.x] = s;
    __syncthreads();
    for (int off = 1; off < SCAN_NT; off <<= 1) {
        int u = (threadIdx.x >= off) ? sh[threadIdx.x - off] : 0;
        __syncthreads();
        sh[threadIdx.x] += u;
        __syncthreads();
    }
    int run = g_bsum[blockIdx.x] + sh[threadIdx.x] - s;
    for (int i = base; i < lim; ++i) {
        int c = g_hist[i];
        g_rowoff[i] = run;
        g_cursor[i] = run;
        run += c;
    }
    if (gid == 0) g_rowoff[n] = m;
}

__global__ void permute_kernel(const int* __restrict__ recv,
                               const int* __restrict__ send, int m) {
    int e = blockIdx.x * blockDim.x + threadIdx.x;
    if (e >= m) return;
    int r = recv[e];
    int pos = atomicAdd(&g_cursor[r], 1);
    g_send_s[pos] = send[e];
}

// ---------------- weight transpose + fp16 ----------------
__global__ void conv_w(const float* w0, const float* w1, const float* w2,
                       const float* w3, const float* w4) {
    __shared__ float t[32][33];
    const float* W = (blockIdx.z == 0) ? w0 : (blockIdx.z == 1) ? w1 :
                     (blockIdx.z == 2) ? w2 : (blockIdx.z == 3) ? w3 : w4;
    int k0 = blockIdx.y * 32, n0 = blockIdx.x * 32;
    t[threadIdx.y][threadIdx.x] = W[(size_t)(k0 + threadIdx.y) * 256 + n0 + threadIdx.x];
    __syncthreads();
    g_WT[(size_t)blockIdx.z * 65536 + (size_t)(n0 + threadIdx.y) * 256 + k0 + threadIdx.x] =
        __float2half_rn(t[threadIdx.x][threadIdx.y]);
}

// ---------------- fp16 tensor-core GEMM, fp32 A (reg-staged cvt) + cp.async W ----------------
struct GemmSet { const __half* WT; const float* b; void* C; };

#define TS 40   // pipeline smem stride (halves)
#define HS 264  // h1 smem stride (halves)

template<bool OUT_HALF>
__global__ __launch_bounds__(256)
void gemm_h(const float* __restrict__ A,
            GemmSet s0, GemmSet s1, GemmSet s2, int nrows)
{
    __shared__ __align__(16) __half As[2][128 * TS];
    __shared__ __align__(16) __half Ws[2][128 * TS];

    const GemmSet gs = (blockIdx.z == 0) ? s0 : (blockIdx.z == 1) ? s1 : s2;
    const __half* __restrict__ WT  = gs.WT;
    const float* __restrict__ bias = gs.b;

    const int tid  = threadIdx.x;
    const int lane = tid & 31;
    const int warp = tid >> 5;
    const int wm   = warp >> 2;
    const int wn   = warp & 3;
    const int m0   = blockIdx.x * 128;
    const int n0   = blockIdx.y * 128;
    const int g    = lane >> 2;
    const int t2   = (lane & 3) * 2;

    const int arow = ((lane >> 3) & 1) * 8 + (lane & 7);
    const int acol = (lane >> 4) * 8;
    const int brow = (lane >> 4) * 8 + (lane & 7);
    const int bcol = ((lane >> 3) & 1) * 8;

    const int lrow = tid >> 2;   // W loader
    const int lkv  = tid & 3;
    const int frow = tid >> 1;   // A loader: 2 threads/row
    const int fc   = (tid & 1) * 4;  // float4 base {0,4}

    float acc[4][4][4];
#pragma unroll
    for (int i = 0; i < 4; i++)
#pragma unroll
        for (int j = 0; j < 4; j++)
#pragma unroll
            for (int k = 0; k < 4; k++) acc[i][j][k] = 0.f;

    float4 areg[4];
    auto ldg_A = [&](int k0) {
        int gm = m0 + frow;
        if (gm < nrows) {
            const float4* src = (const float4*)(A + (size_t)gm * 256 + k0) + fc;
            areg[0] = src[0]; areg[1] = src[1]; areg[2] = src[2]; areg[3] = src[3];
        } else {
            float4 z = make_float4(0.f, 0.f, 0.f, 0.f);
            areg[0] = z; areg[1] = z; areg[2] = z; areg[3] = z;
        }
    };
    auto sts_A = [&](int st) {
        __half2 h[8];
#pragma unroll
        for (int i = 0; i < 4; ++i) {
            h[2 * i]     = __floats2half2_rn(areg[i].x, areg[i].y);
            h[2 * i + 1] = __floats2half2_rn(areg[i].z, areg[i].w);
        }
        *(uint4*)&As[st][frow * TS + fc * 4]     = *(uint4*)&h[0];
        *(uint4*)&As[st][frow * TS + fc * 4 + 8] = *(uint4*)&h[4];
    };
    auto ldw = [&](int st, int k0) {
#pragma unroll
        for (int it = 0; it < 2; ++it) {
            int row = it * 64 + lrow;
            cp_async16(&Ws[st][row * TS + lkv * 8],
                       WT + (size_t)(n0 + row) * 256 + k0 + lkv * 8);
        }
    };

    // prologue
    ldg_A(0);
    ldw(0, 0);
    cp_commit();
    sts_A(0);
    cp_wait<0>();
    __syncthreads();

#pragma unroll 1
    for (int kt = 0; kt < 8; ++kt) {
        const int cur = kt & 1;
        if (kt < 7) {
            ldg_A((kt + 1) * 32);
            ldw(cur ^ 1, (kt + 1) * 32);
            cp_commit();
        }

        const __half* Ab = As[cur];
        const __half* Wb = Ws[cur];
#pragma unroll
        for (int ks = 0; ks < 2; ++ks) {
            const int kk = ks * 16;
            unsigned af[4][4];
#pragma unroll
            for (int mt = 0; mt < 4; ++mt)
                ldsm_x4(af[mt][0], af[mt][1], af[mt][2], af[mt][3],
                        &Ab[(wm * 64 + mt * 16 + arow) * TS + kk + acol]);
            unsigned bf[4][2];
#pragma unroll
            for (int ntp = 0; ntp < 2; ++ntp)
                ldsm_x4(bf[2 * ntp][0], bf[2 * ntp][1],
                        bf[2 * ntp + 1][0], bf[2 * ntp + 1][1],
                        &Wb[(wn * 32 + ntp * 16 + brow) * TS + kk + bcol]);
#pragma unroll
            for (int mt = 0; mt < 4; ++mt)
#pragma unroll
                for (int nt = 0; nt < 4; ++nt)
                    mma_f16(acc[mt][nt], af[mt][0], af[mt][1], af[mt][2], af[mt][3],
                            bf[nt][0], bf[nt][1]);
        }
        if (kt < 7) {
            sts_A(cur ^ 1);
            cp_wait<0>();
        }
        __syncthreads();
    }

#pragma unroll
    for (int mt = 0; mt < 4; ++mt) {
#pragma unroll
        for (int nt = 0; nt < 4; ++nt) {
            int c  = n0 + wn * 32 + nt * 8 + t2;
            float2 b = *(const float2*)(bias + c);
            int r0 = m0 + wm * 64 + mt * 16 + g;
#pragma unroll
            for (int h = 0; h < 2; ++h) {
                int gm = r0 + h * 8;
                if (gm < nrows) {
                    float2 o;
                    o.x = acc[mt][nt][h * 2 + 0] + b.x;
                    o.y = acc[mt][nt][h * 2 + 1] + b.y;
                    if (OUT_HALF) {
                        *(__half2*)((__half*)gs.C + (size_t)gm * 256 + c) =
                            __float22half2_rn(o);
                    } else {
                        *(float2*)((float*)gs.C + (size_t)gm * 256 + c) = o;
                    }
                }
            }
        }
    }
}

// ---------------- fused MLP tail: out = relu(relu(agg@Wa+ba)@Wf+bf) + x ----------------
__global__ __launch_bounds__(256)
void mlp_fused(const __half* __restrict__ A,
               const __half* __restrict__ WTa, const float* __restrict__ ba,
               const __half* __restrict__ WTf, const float* __restrict__ bf,
               const float* __restrict__ x, float* __restrict__ out, int nrows)
{
    extern __shared__ __align__(16) char dyn[];
    __half* As = (__half*)dyn;                 // [2][128*TS]
    __half* Ws = As + 2 * 128 * TS;            // [2][128*TS]
    __half* H1 = Ws + 2 * 128 * TS;            // [128][HS]

    const int tid  = threadIdx.x;
    const int lane = tid & 31;
    const int warp = tid >> 5;
    const int wm   = warp >> 2;
    const int wn   = warp & 3;
    const int m0   = blockIdx.x * 128;
    const int g    = lane >> 2;
    const int t2   = (lane & 3) * 2;
    const int arow = ((lane >> 3) & 1) * 8 + (lane & 7);
    const int acol = (lane >> 4) * 8;
    const int brow = (lane >> 4) * 8 + (lane & 7);
    const int bcol = ((lane >> 3) & 1) * 8;
    const int lrow = tid >> 2;
    const int lkv  = tid & 3;

    // ---- stage 1: h1 = relu(A @ Wa + ba) ----
#pragma unroll 1
    for (int nh = 0; nh < 2; ++nh) {
        const int n0 = nh * 128;

        float acc[4][4][4];
#pragma unroll
        for (int i = 0; i < 4; i++)
#pragma unroll
            for (int j = 0; j < 4; j++)
#pragma unroll
                for (int k = 0; k < 4; k++) acc[i][j][k] = 0.f;

        auto load1 = [&](int st, int k0) {
#pragma unroll
            for (int it = 0; it < 2; ++it) {
                int row = it * 64 + lrow;
                int gm  = m0 + row;
                bool ok = gm < nrows;
                const __half* src = A + (size_t)(ok ? gm : 0) * 256 + k0 + lkv * 8;
                cp_async16_pred(&As[st * 128 * TS + row * TS + lkv * 8], src, ok);
            }
#pragma unroll
            for (int it = 0; it < 2; ++it) {
                int row = it * 64 + lrow;
                cp_async16(&Ws[st * 128 * TS + row * TS + lkv * 8],
                           WTa + (size_t)(n0 + row) * 256 + k0 + lkv * 8);
            }
        };
        load1(0, 0);
        cp_commit();

#pragma unroll 1
        for (int kt = 0; kt < 8; ++kt) {
            const int cur = kt & 1;
            if (kt < 7) { load1(cur ^ 1, (kt + 1) * 32); cp_commit(); cp_wait<1>(); }
            else        { cp_wait<0>(); }
            __syncthreads();

            const __half* Ab = As + cur * 128 * TS;
            const __half* Wb = Ws + cur * 128 * TS;
#pragma unroll
            for (int ks = 0; ks < 2; ++ks) {
                const int kk = ks * 16;
                unsigned af[4][4];
#pragma unroll
                for (int mt = 0; mt < 4; ++mt)
                    ldsm_x4(af[mt][0], af[mt][1], af[mt][2], af[mt][3],
                            &Ab[(wm * 64 + mt * 16 + arow) * TS + kk + acol]);
                unsigned bfr[4][2];
#pragma unroll
                for (int ntp = 0; ntp < 2; ++ntp)
                    ldsm_x4(bfr[2 * ntp][0], bfr[2 * ntp][1],
                            bfr[2 * ntp + 1][0], bfr[2 * ntp + 1][1],
                            &Wb[(wn * 32 + ntp * 16 + brow) * TS + kk + bcol]);
#pragma unroll
                for (int mt = 0; mt < 4; ++mt)
#pragma unroll
                    for (int nt = 0; nt < 4; ++nt)
                        mma_f16(acc[mt][nt], af[mt][0], af[mt][1], af[mt][2], af[mt][3],
                                bfr[nt][0], bfr[nt][1]);
            }
            __syncthreads();
        }

#pragma unroll
        for (int mt = 0; mt < 4; ++mt) {
#pragma unroll
            for (int nt = 0; nt < 4; ++nt) {
                int cl = wn * 32 + nt * 8 + t2;
                float2 b = *(const float2*)(ba + n0 + cl);
                int rl = wm * 64 + mt * 16 + g;
#pragma unroll
                for (int h = 0; h < 2; ++h) {
                    float2 o;
                    o.x = fmaxf(acc[mt][nt][h * 2 + 0] + b.x, 0.f);
                    o.y = fmaxf(acc[mt][nt][h * 2 + 1] + b.y, 0.f);
                    *(__half2*)(&H1[(rl + h * 8) * HS + n0 + cl]) = __float22half2_rn(o);
                }
            }
        }
        __syncthreads();
    }

    // ---- stage 2: out = relu(h1 @ Wf + bf) + x ----
#pragma unroll 1
    for (int nh = 0; nh < 2; ++nh) {
        const int n0 = nh * 128;

        float acc[4][4][4];
#pragma unroll
        for (int i = 0; i < 4; i++)
#pragma unroll
            for (int j = 0; j < 4; j++)
#pragma unroll
                for (int k = 0; k < 4; k++) acc[i][j][k] = 0.f;

        auto load2 = [&](int st, int k0) {
#pragma unroll
            for (int it = 0; it < 2; ++it) {
                int row = it * 64 + lrow;
                cp_async16(&Ws[st * 128 * TS + row * TS + lkv * 8],
                           WTf + (size_t)(n0 + row) * 256 + k0 + lkv * 8);
            }
        };
        load2(0, 0);
        cp_commit();

#pragma unroll 1
        for (int kt = 0; kt < 8; ++kt) {
            const int cur = kt & 1;
            if (kt < 7) { load2(cur ^ 1, (kt + 1) * 32); cp_commit(); cp_wait<1>(); }
            else        { cp_wait<0>(); }
            __syncthreads();

            const int k0 = kt * 32;
            const __half* Wb = Ws + cur * 128 * TS;
#pragma unroll
            for (int ks = 0; ks < 2; ++ks) {
                const int kk = ks * 16;
                unsigned af[4][4];
#pragma unroll
                for (int mt = 0; mt < 4; ++mt)
                    ldsm_x4(af[mt][0], af[mt][1], af[mt][2], af[mt][3],
                            &H1[(wm * 64 + mt * 16 + arow) * HS + k0 + kk + acol]);
                unsigned bfr[4][2];
#pragma unroll
                for (int ntp = 0; ntp < 2; ++ntp)
                    ldsm_x4(bfr[2 * ntp][0], bfr[2 * ntp][1],
                            bfr[2 * ntp + 1][0], bfr[2 * ntp + 1][1],
                            &Wb[(wn * 32 + ntp * 16 + brow) * TS + kk + bcol]);
#pragma unroll
                for (int mt = 0; mt < 4; ++mt)
#pragma unroll
                    for (int nt = 0; nt < 4; ++nt)
                        mma_f16(acc[mt][nt], af[mt][0], af[mt][1], af[mt][2], af[mt][3],
                                bfr[nt][0], bfr[nt][1]);
            }
            __syncthreads();
        }

#pragma unroll
        for (int mt = 0; mt < 4; ++mt) {
#pragma unroll
            for (int nt = 0; nt < 4; ++nt) {
                int c  = n0 + wn * 32 + nt * 8 + t2;
                float2 b = *(const float2*)(bf + c);
                int r0 = m0 + wm * 64 + mt * 16 + g;
#pragma unroll
                for (int h = 0; h < 2; ++h) {
                    int gm = r0 + h * 8;
                    if (gm < nrows) {
                        float2 r = *(const float2*)(x + (size_t)gm * 256 + c);
                        float2 o;
                        o.x = fmaxf(acc[mt][nt][h * 2 + 0] + b.x, 0.f) + r.x;
                        o.y = fmaxf(acc[mt][nt][h * 2 + 1] + b.y, 0.f) + r.y;
                        *(float2*)(out + (size_t)gm * 256 + c) = o;
                    }
                }
            }
        }
        __syncthreads();
    }
}

#define MLP_SMEM (2 * 128 * TS * 2 * 2 + 128 * HS * 2)  // 108544 B

// ---------------- node qk: warp per node; Q in registers, K gathered per edge ----------------
__global__ __launch_bounds__(256)
void node_qk(int n)
{
    __shared__ int smax;
    if (threadIdx.x == 0) smax = 0x80000000;
    __syncthreads();

    const int warp = threadIdx.x >> 5;
    const int lane = threadIdx.x & 31;
    const int v = blockIdx.x * 8 + warp;
    const int h = lane >> 2;

    float mx = -1e30f;
    if (v < n) {
        const int off = g_rowoff[v];
        const int end = g_rowoff[v + 1];

        uint4 qu = ((const uint4*)(g_Q + (size_t)v * 256))[lane];
        const __half2* qh = (const __half2*)&qu;
        float qf[8];
#pragma unroll
        for (int i = 0; i < 4; ++i) {
            float2 f = __half22float2(qh[i]);
            qf[2 * i] = f.x; qf[2 * i + 1] = f.y;
        }

        for (int e = off; e < end; e += 2) {
            const bool two = (e + 1 < end);
            const int s0 = g_send_s[e];
            const int s1 = two ? g_send_s[e + 1] : s0;
            uint4 k0 = ((const uint4*)(g_K + (size_t)s0 * 256))[lane];
            uint4 k1 = ((const uint4*)(g_K + (size_t)s1 * 256))[lane];
            const __half2* ka = (const __half2*)&k0;
            const __half2* kb = (const __half2*)&k1;
            float d0 = 0.f, d1 = 0.f;
#pragma unroll
            for (int i = 0; i < 4; ++i) {
                float2 fa = __half22float2(ka[i]);
                float2 fb = __half22float2(kb[i]);
                d0 = fmaf(qf[2 * i], fa.x, d0);
                d0 = fmaf(qf[2 * i + 1], fa.y, d0);
                d1 = fmaf(qf[2 * i], fb.x, d1);
                d1 = fmaf(qf[2 * i + 1], fb.y, d1);
            }
            d0 += __shfl_xor_sync(0xffffffffu, d0, 1);
            d0 += __shfl_xor_sync(0xffffffffu, d0, 2);
            d1 += __shfl_xor_sync(0xffffffffu, d1, 1);
            d1 += __shfl_xor_sync(0xffffffffu, d1, 2);
            if ((lane & 3) == 0) {
                g_att[(size_t)e * 8 + h] = d0;
                if (two) {
                    g_att[(size_t)(e + 1) * 8 + h] = d1;
                    mx = fmaxf(mx, fmaxf(d0, d1));
                } else {
                    mx = fmaxf(mx, d0);
                }
            }
        }
    }
#pragma unroll
    for (int off = 16; off; off >>= 1)
        mx = fmaxf(mx, __shfl_xor_sync(0xffffffffu, mx, off));
    if (lane == 0) atomicMax(&smax, f2ord(mx));
    __syncthreads();
    if (threadIdx.x == 0) atomicMax(&g_maxbits, smax);
}

// ---------------- per-node softmax + aggregation: warp per node, 4-edge unroll ----------------
__global__ __launch_bounds__(256)
void node_msg(int n)
{
    __shared__ float sden[8][8];
    __shared__ float sscale;
    if (threadIdx.x == 0) sscale = 3.0f / ord2f(g_maxbits);
    __syncthreads();
    const float scale = sscale;

    const int warp = threadIdx.x >> 5;
    const int lane = threadIdx.x & 31;
    const int v = blockIdx.x * 8 + warp;
    if (v >= n) return;

    const int off = g_rowoff[v];
    const int end = g_rowoff[v + 1];

    float dsum = 0.f;
    for (int base = off; base < end; base += 4) {
        int e = base + (lane >> 3);
        float a = 0.f;
        if (e < end) a = __expf(g_att[(size_t)e * 8 + (lane & 7)] * scale);
        dsum += a;
    }
    dsum += __shfl_xor_sync(0xffffffffu, dsum, 8);
    dsum += __shfl_xor_sync(0xffffffffu, dsum, 16);
    if (lane < 8) sden[warp][lane] = dsum * 5.656854249492381f;  // fold sqrt(32)
    __syncwarp();

    const int h = lane >> 2;
    const float inv = 1.0f / sden[warp][h];
    float acc[8] = {0.f, 0.f, 0.f, 0.f, 0.f, 0.f, 0.f, 0.f};

    for (int e = off; e < end; e += 4) {
        const int cnt = end - e;
        const int s0 = g_send_s[e];
        const int s1 = cnt > 1 ? g_send_s[e + 1] : s0;
        const int s2 = cnt > 2 ? g_send_s[e + 2] : s0;
        const int s3 = cnt > 3 ? g_send_s[e + 3] : s0;
        uint4 u0 = ((const uint4*)(g_V + (size_t)s0 * 256))[lane];
        uint4 u1 = ((const uint4*)(g_V + (size_t)s1 * 256))[lane];
        uint4 u2 = ((const uint4*)(g_V + (size_t)s2 * 256))[lane];
        uint4 u3 = ((const uint4*)(g_V + (size_t)s3 * 256))[lane];
        float w0 = __expf(g_att[(size_t)e * 8 + h] * scale) * inv;
        float w1 = cnt > 1 ? __expf(g_att[(size_t)(e + 1) * 8 + h] * scale) * inv : 0.f;
        float w2 = cnt > 2 ? __expf(g_att[(size_t)(e + 2) * 8 + h] * scale) * inv : 0.f;
        float w3 = cnt > 3 ? __expf(g_att[(size_t)(e + 3) * 8 + h] * scale) * inv : 0.f;
        const __half2* v0 = (const __half2*)&u0;
        const __half2* v1 = (const __half2*)&u1;
        const __half2* v2 = (const __half2*)&u2;
        const __half2* v3 = (const __half2*)&u3;
#pragma unroll
        for (int i = 0; i < 4; ++i) {
            float2 f0 = __half22float2(v0[i]);
            float2 f1 = __half22float2(v1[i]);
            float2 f2 = __half22float2(v2[i]);
            float2 f3 = __half22float2(v3[i]);
            acc[2 * i]     = fmaf(w0, f0.x, fmaf(w1, f1.x, fmaf(w2, f2.x, fmaf(w3, f3.x, acc[2 * i]))));
            acc[2 * i + 1] = fmaf(w0, f0.y, fmaf(w1, f1.y, fmaf(w2, f2.y, fmaf(w3, f3.y, acc[2 * i + 1]))));
        }
    }

    __half2 h0 = __floats2half2_rn(fmaxf(acc[0], 0.f), fmaxf(acc[1], 0.f));
    __half2 h1 = __floats2half2_rn(fmaxf(acc[2], 0.f), fmaxf(acc[3], 0.f));
    __half2 h2 = __floats2half2_rn(fmaxf(acc[4], 0.f), fmaxf(acc[5], 0.f));
    __half2 h3 = __floats2half2_rn(fmaxf(acc[6], 0.f), fmaxf(acc[7], 0.f));
    __half2* Ap = (__half2*)(g_agg + (size_t)v * 256 + lane * 8);
    Ap[0] = h0; Ap[1] = h1; Ap[2] = h2; Ap[3] = h3;
}

// ---------------- side stream / events / attrs (created once, before any capture) ----------------
struct Aux {
    cudaStream_t s2;
    cudaEvent_t evFork, evW, evCSR, evV;
    Aux() {
        cudaStreamCreateWithFlags(&s2, cudaStreamNonBlocking);
        cudaEventCreateWithFlags(&evFork, cudaEventDisableTiming);
        cudaEventCreateWithFlags(&evW,    cudaEventDisableTiming);
        cudaEventCreateWithFlags(&evCSR,  cudaEventDisableTiming);
        cudaEventCreateWithFlags(&evV,    cudaEventDisableTiming);
        cudaFuncSetAttribute(mlp_fused,
                             cudaFuncAttributeMaxDynamicSharedMemorySize, MLP_SMEM);
    }
};
static Aux g_aux;

// ---------------- launch ----------------
extern "C" void kernel_launch(void* const* d_in, const int* in_sizes, int n_in,
                              void* d_out, int out_size)
{
    const float* x    = (const float*)d_in[0];
    const int*   ei   = (const int*)d_in[1];
    const float* Wk   = (const float*)d_in[2];
    const float* bk   = (const float*)d_in[3];
    const float* Wq   = (const float*)d_in[4];
    const float* bq   = (const float*)d_in[5];
    const float* Wv   = (const float*)d_in[6];
    const float* bv   = (const float*)d_in[7];
    const float* Wagg = (const float*)d_in[8];
    const float* bagg = (const float*)d_in[9];
    const float* Wff  = (const float*)d_in[10];
    const float* bff  = (const float*)d_in[11];
    float* out = (float*)d_out;

    const int n = in_sizes[0] / 256;
    const int m = in_sizes[1] / 2;
    const int* recv = ei;
    const int* send = ei + m;

    __half *Qp, *Kp, *Vp, *aggp, *WTp;
    cudaGetSymbolAddress((void**)&Qp,   g_Q);
    cudaGetSymbolAddress((void**)&Kp,   g_K);
    cudaGetSymbolAddress((void**)&Vp,   g_V);
    cudaGetSymbolAddress((void**)&aggp, g_agg);
    cudaGetSymbolAddress((void**)&WTp,  g_WT);

    cudaStream_t s2 = g_aux.s2;
    const int gx = (n + 127) / 128;

    // fork side branch
    cudaEventRecord(g_aux.evFork, 0);
    cudaStreamWaitEvent(s2, g_aux.evFork, 0);

    // side: weight conversion (evW gates QK on main), CSR build, V projection
    conv_w<<<dim3(8, 8, 5), dim3(32, 32), 0, s2>>>(Wq, Wk, Wv, Wagg, Wff);
    cudaEventRecord(g_aux.evW, s2);
    init_kernel<<<(n + 255) / 256, 256, 0, s2>>>(n);
    hist_kernel<<<(m + 255) / 256, 256, 0, s2>>>(recv, m);
    scan_p1<<<SCAN_NB, SCAN_NT, 0, s2>>>(n);
    scan_p2<<<1, SCAN_NB, 0, s2>>>();
    scan_p3<<<SCAN_NB, SCAN_NT, 0, s2>>>(n, m);
    permute_kernel<<<(m + 255) / 256, 256, 0, s2>>>(recv, send, m);
    cudaEventRecord(g_aux.evCSR, s2);

    GemmSet sv = {WTp + 2 * 65536, bv, Vp};
    gemm_h<true><<<dim3(gx, 2, 1), 256, 0, s2>>>(x, sv, sv, sv, n);
    cudaEventRecord(g_aux.evV, s2);

    // main: Q/K projections (wait only for the weight conversion)
    cudaStreamWaitEvent(0, g_aux.evW, 0);
    GemmSet sq = {WTp,         bq, Qp};
    GemmSet sk = {WTp + 65536, bk, Kp};
    gemm_h<true><<<dim3(gx, 2, 2), 256>>>(x, sq, sk, sk, n);

    // join CSR, then node-centric edge logits
    cudaStreamWaitEvent(0, g_aux.evCSR, 0);
    node_qk<<<(n + 7) / 8, 256>>>(n);

    // join V, then aggregation
    cudaStreamWaitEvent(0, g_aux.evV, 0);
    node_msg<<<(n + 7) / 8, 256>>>(n);

    // fused MLP tail
    mlp_fused<<<gx, 256, MLP_SMEM>>>(aggp, WTp + 3 * 65536, bagg,
                                     WTp + 4 * 65536, bff, x, out, n);
}

// round 13
// speedup vs baseline: 1.0133x; 1.0133x over previous
#include <cuda_runtime.h>
#include <cuda_fp16.h>
#include <math.h>

#define NMAX 50000
#define MMAX 800000
#define DD 256

// ---------------- scratch (static device globals; no allocation) ----------------
__device__ __align__(16) __half g_xh[(size_t)NMAX * DD];   // x in fp16 (GEMM A)
__device__ __align__(16) __half g_Q[(size_t)NMAX * DD];
__device__ __align__(16) __half g_K[(size_t)NMAX * DD];
__device__ __align__(16) __half g_V[(size_t)NMAX * DD];
__device__ __align__(16) __half g_agg[(size_t)NMAX * DD];  // relu'd messages (fp16)
__device__ __align__(16) __half g_WT[5 * 65536];           // weights fp16, [n][k]
__device__ __align__(16) float  g_att[(size_t)MMAX * 8];   // qk logits (CSR edge order)
__device__ int g_hist[NMAX];
__device__ int g_cursor[NMAX];
__device__ int g_rowoff[NMAX + 1];
__device__ int g_send_s[MMAX];
__device__ int g_bsum[64];
__device__ int g_maxbits;

__device__ __forceinline__ int f2ord(float f) {
    int b = __float_as_int(f);
    return b >= 0 ? b : (b ^ 0x7FFFFFFF);
}
__device__ __forceinline__ float ord2f(int b) {
    return __int_as_float(b >= 0 ? b : (b ^ 0x7FFFFFFF));
}

__device__ __forceinline__ void mma_f16(float* c, unsigned a0, unsigned a1,
                                        unsigned a2, unsigned a3,
                                        unsigned b0, unsigned b1) {
    asm volatile(
        "mma.sync.aligned.m16n8k16.row.col.f32.f16.f16.f32 "
        "{%0,%1,%2,%3}, {%4,%5,%6,%7}, {%8,%9}, {%0,%1,%2,%3};"
        : "+f"(c[0]), "+f"(c[1]), "+f"(c[2]), "+f"(c[3])
        : "r"(a0), "r"(a1), "r"(a2), "r"(a3), "r"(b0), "r"(b1));
}

__device__ __forceinline__ void ldsm_x4(unsigned& r0, unsigned& r1,
                                        unsigned& r2, unsigned& r3, const __half* p) {
    unsigned a = (unsigned)__cvta_generic_to_shared(p);
    asm volatile("ldmatrix.sync.aligned.m8n8.x4.shared.b16 {%0,%1,%2,%3}, [%4];"
                 : "=r"(r0), "=r"(r1), "=r"(r2), "=r"(r3) : "r"(a));
}

__device__ __forceinline__ void cp_async16(void* smem, const void* gmem) {
    unsigned sa = (unsigned)__cvta_generic_to_shared(smem);
    asm volatile("cp.async.cg.shared.global [%0], [%1], 16;" :: "r"(sa), "l"(gmem));
}
__device__ __forceinline__ void cp_async16_pred(void* smem, const void* gmem, bool p) {
    unsigned sa = (unsigned)__cvta_generic_to_shared(smem);
    int sz = p ? 16 : 0;
    asm volatile("cp.async.cg.shared.global [%0], [%1], 16, %2;"
                 :: "r"(sa), "l"(gmem), "r"(sz));
}
__device__ __forceinline__ void cp_commit() {
    asm volatile("cp.async.commit_group;");
}
template<int N>
__device__ __forceinline__ void cp_wait() {
    asm volatile("cp.async.wait_group %0;" :: "n"(N));
}

// ---------------- CSR build ----------------
__global__ void init_kernel(int n) {
    int i = blockIdx.x * blockDim.x + threadIdx.x;
    if (i < n) g_hist[i] = 0;
    if (i == 0) g_maxbits = 0x80000000;
}

__global__ void hist_kernel(const int* __restrict__ recv, int m) {
    int i = blockIdx.x * blockDim.x + threadIdx.x;
    if (i < m) atomicAdd(&g_hist[recv[i]], 1);
}

#define SCAN_NB 64
#define SCAN_NT 256

__global__ __launch_bounds__(SCAN_NT)
void scan_p1(int n) {
    __shared__ int sh[SCAN_NT];
    const int chunk = (n + SCAN_NB * SCAN_NT - 1) / (SCAN_NB * SCAN_NT);
    const int gid = blockIdx.x * SCAN_NT + threadIdx.x;
    const int base = gid * chunk;
    const int lim = min(base + chunk, n);
    int s = 0;
    for (int i = base; i < lim; ++i) s += g_hist[i];
    sh[threadIdx.x] = s;
    __syncthreads();
    for (int off = SCAN_NT / 2; off; off >>= 1) {
        if (threadIdx.x < off) sh[threadIdx.x] += sh[threadIdx.x + off];
        __syncthreads();
    }
    if (threadIdx.x == 0) g_bsum[blockIdx.x] = sh[0];
}

__global__ __launch_bounds__(SCAN_NB)
void scan_p2() {
    __shared__ int sh[SCAN_NB];
    const int t = threadIdx.x;
    int v = g_bsum[t];
    sh[t] = v;
    __syncthreads();
    for (int off = 1; off < SCAN_NB; off <<= 1) {
        int u = (t >= off) ? sh[t - off] : 0;
        __syncthreads();
        sh[t] += u;
        __syncthreads();
    }
    g_bsum[t] = sh[t] - v;
}

__global__ __launch_bounds__(SCAN_NT)
void scan_p3(int n, int m) {
    __shared__ int sh[SCAN_NT];
    const int chunk = (n + SCAN_NB * SCAN_NT - 1) / (SCAN_NB * SCAN_NT);
    const int gid = blockIdx.x * SCAN_NT + threadIdx.x;
    const int base = gid * chunk;
    const int lim = min(base + chunk, n);
    int s = 0;
    for (int i = base; i < lim; ++i) s += g_hist[i];
    sh[threadIdx.x] = s;
    __syncthreads();
    for (int off = 1; off < SCAN_NT; off <<= 1) {
        int u = (threadIdx.x >= off) ? sh[threadIdx.x - off] : 0;
        __syncthreads();
        sh[threadIdx.x] += u;
        __syncthreads();
    }
    int run = g_bsum[blockIdx.x] + sh[threadIdx.x] - s;
    for (int i = base; i < lim; ++i) {
        int c = g_hist[i];
        g_rowoff[i] = run;
        g_cursor[i] = run;
        run += c;
    }
    if (gid == 0) g_rowoff[n] = m;
}

__global__ void permute_kernel(const int* __restrict__ recv,
                               const int* __restrict__ send, int m) {
    int e = blockIdx.x * blockDim.x + threadIdx.x;
    if (e >= m) return;
    int r = recv[e];
    int pos = atomicAdd(&g_cursor[r], 1);
    g_send_s[pos] = send[e];
}

// ---------------- conversions ----------------
__global__ void conv_x(const float* __restrict__ x, int n4) {
    int i = blockIdx.x * blockDim.x + threadIdx.x;
    if (i >= n4) return;
    float4 v = ((const float4*)x)[i];
    ((__half2*)g_xh)[2 * i]     = __floats2half2_rn(v.x, v.y);
    ((__half2*)g_xh)[2 * i + 1] = __floats2half2_rn(v.z, v.w);
}

__global__ void conv_w(const float* w0, const float* w1, const float* w2,
                       const float* w3, const float* w4) {
    __shared__ float t[32][33];
    const float* W = (blockIdx.z == 0) ? w0 : (blockIdx.z == 1) ? w1 :
                     (blockIdx.z == 2) ? w2 : (blockIdx.z == 3) ? w3 : w4;
    int k0 = blockIdx.y * 32, n0 = blockIdx.x * 32;
    t[threadIdx.y][threadIdx.x] = W[(size_t)(k0 + threadIdx.y) * 256 + n0 + threadIdx.x];
    __syncthreads();
    g_WT[(size_t)blockIdx.z * 65536 + (size_t)(n0 + threadIdx.y) * 256 + k0 + threadIdx.x] =
        __float2half_rn(t[threadIdx.x][threadIdx.y]);
}

// ---------------- fp16 tensor-core GEMM, cp.async + ldmatrix ----------------
struct GemmSet { const __half* WT; const float* b; void* C; };

#define TS 40   // pipeline smem stride (halves)
#define HS 264  // h1 smem stride (halves)

template<bool OUT_HALF>
__global__ __launch_bounds__(256)
void gemm_h(const __half* __restrict__ A,
            GemmSet s0, GemmSet s1, GemmSet s2, int nrows)
{
    __shared__ __align__(16) __half As[2][128 * TS];
    __shared__ __align__(16) __half Ws[2][128 * TS];

    const GemmSet gs = (blockIdx.z == 0) ? s0 : (blockIdx.z == 1) ? s1 : s2;
    const __half* __restrict__ WT  = gs.WT;
    const float* __restrict__ bias = gs.b;

    const int tid  = threadIdx.x;
    const int lane = tid & 31;
    const int warp = tid >> 5;
    const int wm   = warp >> 2;
    const int wn   = warp & 3;
    const int m0   = blockIdx.x * 128;
    const int n0   = blockIdx.y * 128;
    const int g    = lane >> 2;
    const int t2   = (lane & 3) * 2;

    const int arow = ((lane >> 3) & 1) * 8 + (lane & 7);
    const int acol = (lane >> 4) * 8;
    const int brow = (lane >> 4) * 8 + (lane & 7);
    const int bcol = ((lane >> 3) & 1) * 8;

    const int lrow = tid >> 2;
    const int lkv  = tid & 3;

    float acc[4][4][4];
#pragma unroll
    for (int i = 0; i < 4; i++)
#pragma unroll
        for (int j = 0; j < 4; j++)
#pragma unroll
            for (int k = 0; k < 4; k++) acc[i][j][k] = 0.f;

    auto load_tiles = [&](int st, int k0) {
#pragma unroll
        for (int it = 0; it < 2; ++it) {
            int row = it * 64 + lrow;
            int gm  = m0 + row;
            bool ok = gm < nrows;
            const __half* src = A + (size_t)(ok ? gm : 0) * 256 + k0 + lkv * 8;
            cp_async16_pred(&As[st][row * TS + lkv * 8], src, ok);
        }
#pragma unroll
        for (int it = 0; it < 2; ++it) {
            int row = it * 64 + lrow;
            cp_async16(&Ws[st][row * TS + lkv * 8],
                       WT + (size_t)(n0 + row) * 256 + k0 + lkv * 8);
        }
    };

    load_tiles(0, 0);
    cp_commit();

#pragma unroll 1
    for (int kt = 0; kt < 8; ++kt) {
        const int cur = kt & 1;
        if (kt < 7) {
            load_tiles(cur ^ 1, (kt + 1) * 32);
            cp_commit();
            cp_wait<1>();
        } else {
            cp_wait<0>();
        }
        __syncthreads();

        const __half* Ab = As[cur];
        const __half* Wb = Ws[cur];
#pragma unroll
        for (int ks = 0; ks < 2; ++ks) {
            const int kk = ks * 16;
            unsigned af[4][4];
#pragma unroll
            for (int mt = 0; mt < 4; ++mt)
                ldsm_x4(af[mt][0], af[mt][1], af[mt][2], af[mt][3],
                        &Ab[(wm * 64 + mt * 16 + arow) * TS + kk + acol]);
            unsigned bf[4][2];
#pragma unroll
            for (int ntp = 0; ntp < 2; ++ntp)
                ldsm_x4(bf[2 * ntp][0], bf[2 * ntp][1],
                        bf[2 * ntp + 1][0], bf[2 * ntp + 1][1],
                        &Wb[(wn * 32 + ntp * 16 + brow) * TS + kk + bcol]);
#pragma unroll
            for (int mt = 0; mt < 4; ++mt)
#pragma unroll
                for (int nt = 0; nt < 4; ++nt)
                    mma_f16(acc[mt][nt], af[mt][0], af[mt][1], af[mt][2], af[mt][3],
                            bf[nt][0], bf[nt][1]);
        }
        __syncthreads();
    }

#pragma unroll
    for (int mt = 0; mt < 4; ++mt) {
#pragma unroll
        for (int nt = 0; nt < 4; ++nt) {
            int c  = n0 + wn * 32 + nt * 8 + t2;
            float2 b = *(const float2*)(bias + c);
            int r0 = m0 + wm * 64 + mt * 16 + g;
#pragma unroll
            for (int h = 0; h < 2; ++h) {
                int gm = r0 + h * 8;
                if (gm < nrows) {
                    float2 o;
                    o.x = acc[mt][nt][h * 2 + 0] + b.x;
                    o.y = acc[mt][nt][h * 2 + 1] + b.y;
                    if (OUT_HALF) {
                        *(__half2*)((__half*)gs.C + (size_t)gm * 256 + c) =
                            __float22half2_rn(o);
                    } else {
                        *(float2*)((float*)gs.C + (size_t)gm * 256 + c) = o;
                    }
                }
            }
        }
    }
}

// ---------------- fused MLP tail: out = relu(relu(agg@Wa+ba)@Wf+bf) + x ----------------
__global__ __launch_bounds__(256)
void mlp_fused(const __half* __restrict__ A,
               const __half* __restrict__ WTa, const float* __restrict__ ba,
               const __half* __restrict__ WTf, const float* __restrict__ bf,
               const float* __restrict__ x, float* __restrict__ out, int nrows)
{
    extern __shared__ __align__(16) char dyn[];
    __half* As = (__half*)dyn;                 // [2][128*TS]
    __half* Ws = As + 2 * 128 * TS;            // [2][128*TS]
    __half* H1 = Ws + 2 * 128 * TS;            // [128][HS]

    const int tid  = threadIdx.x;
    const int lane = tid & 31;
    const int warp = tid >> 5;
    const int wm   = warp >> 2;
    const int wn   = warp & 3;
    const int m0   = blockIdx.x * 128;
    const int g    = lane >> 2;
    const int t2   = (lane & 3) * 2;
    const int arow = ((lane >> 3) & 1) * 8 + (lane & 7);
    const int acol = (lane >> 4) * 8;
    const int brow = (lane >> 4) * 8 + (lane & 7);
    const int bcol = ((lane >> 3) & 1) * 8;
    const int lrow = tid >> 2;
    const int lkv  = tid & 3;

    // ---- stage 1: h1 = relu(A @ Wa + ba) ----
#pragma unroll 1
    for (int nh = 0; nh < 2; ++nh) {
        const int n0 = nh * 128;

        float acc[4][4][4];
#pragma unroll
        for (int i = 0; i < 4; i++)
#pragma unroll
            for (int j = 0; j < 4; j++)
#pragma unroll
                for (int k = 0; k < 4; k++) acc[i][j][k] = 0.f;

        auto load1 = [&](int st, int k0) {
#pragma unroll
            for (int it = 0; it < 2; ++it) {
                int row = it * 64 + lrow;
                int gm  = m0 + row;
                bool ok = gm < nrows;
                const __half* src = A + (size_t)(ok ? gm : 0) * 256 + k0 + lkv * 8;
                cp_async16_pred(&As[st * 128 * TS + row * TS + lkv * 8], src, ok);
            }
#pragma unroll
            for (int it = 0; it < 2; ++it) {
                int row = it * 64 + lrow;
                cp_async16(&Ws[st * 128 * TS + row * TS + lkv * 8],
                           WTa + (size_t)(n0 + row) * 256 + k0 + lkv * 8);
            }
        };
        load1(0, 0);
        cp_commit();

#pragma unroll 1
        for (int kt = 0; kt < 8; ++kt) {
            const int cur = kt & 1;
            if (kt < 7) { load1(cur ^ 1, (kt + 1) * 32); cp_commit(); cp_wait<1>(); }
            else        { cp_wait<0>(); }
            __syncthreads();

            const __half* Ab = As + cur * 128 * TS;
            const __half* Wb = Ws + cur * 128 * TS;
#pragma unroll
            for (int ks = 0; ks < 2; ++ks) {
                const int kk = ks * 16;
                unsigned af[4][4];
#pragma unroll
                for (int mt = 0; mt < 4; ++mt)
                    ldsm_x4(af[mt][0], af[mt][1], af[mt][2], af[mt][3],
                            &Ab[(wm * 64 + mt * 16 + arow) * TS + kk + acol]);
                unsigned bfr[4][2];
#pragma unroll
                for (int ntp = 0; ntp < 2; ++ntp)
                    ldsm_x4(bfr[2 * ntp][0], bfr[2 * ntp][1],
                            bfr[2 * ntp + 1][0], bfr[2 * ntp + 1][1],
                            &Wb[(wn * 32 + ntp * 16 + brow) * TS + kk + bcol]);
#pragma unroll
                for (int mt = 0; mt < 4; ++mt)
#pragma unroll
                    for (int nt = 0; nt < 4; ++nt)
                        mma_f16(acc[mt][nt], af[mt][0], af[mt][1], af[mt][2], af[mt][3],
                                bfr[nt][0], bfr[nt][1]);
            }
            __syncthreads();
        }

#pragma unroll
        for (int mt = 0; mt < 4; ++mt) {
#pragma unroll
            for (int nt = 0; nt < 4; ++nt) {
                int cl = wn * 32 + nt * 8 + t2;
                float2 b = *(const float2*)(ba + n0 + cl);
                int rl = wm * 64 + mt * 16 + g;
#pragma unroll
                for (int h = 0; h < 2; ++h) {
                    float2 o;
                    o.x = fmaxf(acc[mt][nt][h * 2 + 0] + b.x, 0.f);
                    o.y = fmaxf(acc[mt][nt][h * 2 + 1] + b.y, 0.f);
                    *(__half2*)(&H1[(rl + h * 8) * HS + n0 + cl]) = __float22half2_rn(o);
                }
            }
        }
        __syncthreads();
    }

    // ---- stage 2: out = relu(h1 @ Wf + bf) + x ----
#pragma unroll 1
    for (int nh = 0; nh < 2; ++nh) {
        const int n0 = nh * 128;

        float acc[4][4][4];
#pragma unroll
        for (int i = 0; i < 4; i++)
#pragma unroll
            for (int j = 0; j < 4; j++)
#pragma unroll
                for (int k = 0; k < 4; k++) acc[i][j][k] = 0.f;

        auto load2 = [&](int st, int k0) {
#pragma unroll
            for (int it = 0; it < 2; ++it) {
                int row = it * 64 + lrow;
                cp_async16(&Ws[st * 128 * TS + row * TS + lkv * 8],
                           WTf + (size_t)(n0 + row) * 256 + k0 + lkv * 8);
            }
        };
        load2(0, 0);
        cp_commit();

#pragma unroll 1
        for (int kt = 0; kt < 8; ++kt) {
            const int cur = kt & 1;
            if (kt < 7) { load2(cur ^ 1, (kt + 1) * 32); cp_commit(); cp_wait<1>(); }
            else        { cp_wait<0>(); }
            __syncthreads();

            const int k0 = kt * 32;
            const __half* Wb = Ws + cur * 128 * TS;
#pragma unroll
            for (int ks = 0; ks < 2; ++ks) {
                const int kk = ks * 16;
                unsigned af[4][4];
#pragma unroll
                for (int mt = 0; mt < 4; ++mt)
                    ldsm_x4(af[mt][0], af[mt][1], af[mt][2], af[mt][3],
                            &H1[(wm * 64 + mt * 16 + arow) * HS + k0 + kk + acol]);
                unsigned bfr[4][2];
#pragma unroll
                for (int ntp = 0; ntp < 2; ++ntp)
                    ldsm_x4(bfr[2 * ntp][0], bfr[2 * ntp][1],
                            bfr[2 * ntp + 1][0], bfr[2 * ntp + 1][1],
                            &Wb[(wn * 32 + ntp * 16 + brow) * TS + kk + bcol]);
#pragma unroll
                for (int mt = 0; mt < 4; ++mt)
#pragma unroll
                    for (int nt = 0; nt < 4; ++nt)
                        mma_f16(acc[mt][nt], af[mt][0], af[mt][1], af[mt][2], af[mt][3],
                                bfr[nt][0], bfr[nt][1]);
            }
            __syncthreads();
        }

#pragma unroll
        for (int mt = 0; mt < 4; ++mt) {
#pragma unroll
            for (int nt = 0; nt < 4; ++nt) {
                int c  = n0 + wn * 32 + nt * 8 + t2;
                float2 b = *(const float2*)(bf + c);
                int r0 = m0 + wm * 64 + mt * 16 + g;
#pragma unroll
                for (int h = 0; h < 2; ++h) {
                    int gm = r0 + h * 8;
                    if (gm < nrows) {
                        float2 r = *(const float2*)(x + (size_t)gm * 256 + c);
                        float2 o;
                        o.x = fmaxf(acc[mt][nt][h * 2 + 0] + b.x, 0.f) + r.x;
                        o.y = fmaxf(acc[mt][nt][h * 2 + 1] + b.y, 0.f) + r.y;
                        *(float2*)(out + (size_t)gm * 256 + c) = o;
                    }
                }
            }
        }
        __syncthreads();
    }
}

#define MLP_SMEM (2 * 128 * TS * 2 * 2 + 128 * HS * 2)  // 108544 B

// ---------------- node qk: warp per node; Q in registers, 4 K gathers in flight ----------------
__global__ __launch_bounds__(256)
void node_qk(int n)
{
    __shared__ int smax;
    if (threadIdx.x == 0) smax = 0x80000000;
    __syncthreads();

    const int warp = threadIdx.x >> 5;
    const int lane = threadIdx.x & 31;
    const int v = blockIdx.x * 8 + warp;
    const int h = lane >> 2;

    float mx = -1e30f;
    if (v < n) {
        const int off = g_rowoff[v];
        const int end = g_rowoff[v + 1];

        uint4 qu = ((const uint4*)(g_Q + (size_t)v * 256))[lane];
        const __half2* qh = (const __half2*)&qu;
        float qf[8];
#pragma unroll
        for (int i = 0; i < 4; ++i) {
            float2 f = __half22float2(qh[i]);
            qf[2 * i] = f.x; qf[2 * i + 1] = f.y;
        }

        for (int e = off; e < end; e += 4) {
            const int cnt = end - e;
            const int s0 = g_send_s[e];
            const int s1 = cnt > 1 ? g_send_s[e + 1] : s0;
            const int s2 = cnt > 2 ? g_send_s[e + 2] : s0;
            const int s3 = cnt > 3 ? g_send_s[e + 3] : s0;
            uint4 k0 = ((const uint4*)(g_K + (size_t)s0 * 256))[lane];
            uint4 k1 = ((const uint4*)(g_K + (size_t)s1 * 256))[lane];
            uint4 k2 = ((const uint4*)(g_K + (size_t)s2 * 256))[lane];
            uint4 k3 = ((const uint4*)(g_K + (size_t)s3 * 256))[lane];
            const __half2* ka = (const __half2*)&k0;
            const __half2* kb = (const __half2*)&k1;
            const __half2* kc = (const __half2*)&k2;
            const __half2* kd = (const __half2*)&k3;
            float d0 = 0.f, d1 = 0.f, d2 = 0.f, d3 = 0.f;
#pragma unroll
            for (int i = 0; i < 4; ++i) {
                float2 fa = __half22float2(ka[i]);
                float2 fb = __half22float2(kb[i]);
                float2 fc = __half22float2(kc[i]);
                float2 fd = __half22float2(kd[i]);
                d0 = fmaf(qf[2 * i], fa.x, d0); d0 = fmaf(qf[2 * i + 1], fa.y, d0);
                d1 = fmaf(qf[2 * i], fb.x, d1); d1 = fmaf(qf[2 * i + 1], fb.y, d1);
                d2 = fmaf(qf[2 * i], fc.x, d2); d2 = fmaf(qf[2 * i + 1], fc.y, d2);
                d3 = fmaf(qf[2 * i], fd.x, d3); d3 = fmaf(qf[2 * i + 1], fd.y, d3);
            }
            d0 += __shfl_xor_sync(0xffffffffu, d0, 1);
            d0 += __shfl_xor_sync(0xffffffffu, d0, 2);
            d1 += __shfl_xor_sync(0xffffffffu, d1, 1);
            d1 += __shfl_xor_sync(0xffffffffu, d1, 2);
            d2 += __shfl_xor_sync(0xffffffffu, d2, 1);
            d2 += __shfl_xor_sync(0xffffffffu, d2, 2);
            d3 += __shfl_xor_sync(0xffffffffu, d3, 1);
            d3 += __shfl_xor_sync(0xffffffffu, d3, 2);
            if ((lane & 3) == 0) {
                g_att[(size_t)e * 8 + h] = d0;
                mx = fmaxf(mx, d0);
                if (cnt > 1) { g_att[(size_t)(e + 1) * 8 + h] = d1; mx = fmaxf(mx, d1); }
                if (cnt > 2) { g_att[(size_t)(e + 2) * 8 + h] = d2; mx = fmaxf(mx, d2); }
                if (cnt > 3) { g_att[(size_t)(e + 3) * 8 + h] = d3; mx = fmaxf(mx, d3); }
            }
        }
    }
#pragma unroll
    for (int off = 16; off; off >>= 1)
        mx = fmaxf(mx, __shfl_xor_sync(0xffffffffu, mx, off));
    if (lane == 0) atomicMax(&smax, f2ord(mx));
    __syncthreads();
    if (threadIdx.x == 0) atomicMax(&g_maxbits, smax);
}

// ---------------- per-node softmax + aggregation: warp per node, 4-edge unroll ----------------
__global__ __launch_bounds__(256)
void node_msg(int n)
{
    __shared__ float sden[8][8];
    __shared__ float sscale;
    if (threadIdx.x == 0) sscale = 3.0f / ord2f(g_maxbits);
    __syncthreads();
    const float scale = sscale;

    const int warp = threadIdx.x >> 5;
    const int lane = threadIdx.x & 31;
    const int v = blockIdx.x * 8 + warp;
    if (v >= n) return;

    const int off = g_rowoff[v];
    const int end = g_rowoff[v + 1];

    float dsum = 0.f;
    for (int base = off; base < end; base += 4) {
        int e = base + (lane >> 3);
        float a = 0.f;
        if (e < end) a = __expf(g_att[(size_t)e * 8 + (lane & 7)] * scale);
        dsum += a;
    }
    dsum += __shfl_xor_sync(0xffffffffu, dsum, 8);
    dsum += __shfl_xor_sync(0xffffffffu, dsum, 16);
    if (lane < 8) sden[warp][lane] = dsum * 5.656854249492381f;  // fold sqrt(32)
    __syncwarp();

    const int h = lane >> 2;
    const float inv = 1.0f / sden[warp][h];
    float acc[8] = {0.f, 0.f, 0.f, 0.f, 0.f, 0.f, 0.f, 0.f};

    for (int e = off; e < end; e += 4) {
        const int cnt = end - e;
        const int s0 = g_send_s[e];
        const int s1 = cnt > 1 ? g_send_s[e + 1] : s0;
        const int s2 = cnt > 2 ? g_send_s[e + 2] : s0;
        const int s3 = cnt > 3 ? g_send_s[e + 3] : s0;
        uint4 u0 = ((const uint4*)(g_V + (size_t)s0 * 256))[lane];
        uint4 u1 = ((const uint4*)(g_V + (size_t)s1 * 256))[lane];
        uint4 u2 = ((const uint4*)(g_V + (size_t)s2 * 256))[lane];
        uint4 u3 = ((const uint4*)(g_V + (size_t)s3 * 256))[lane];
        float w0 = __expf(g_att[(size_t)e * 8 + h] * scale) * inv;
        float w1 = cnt > 1 ? __expf(g_att[(size_t)(e + 1) * 8 + h] * scale) * inv : 0.f;
        float w2 = cnt > 2 ? __expf(g_att[(size_t)(e + 2) * 8 + h] * scale) * inv : 0.f;
        float w3 = cnt > 3 ? __expf(g_att[(size_t)(e + 3) * 8 + h] * scale) * inv : 0.f;
        const __half2* v0 = (const __half2*)&u0;
        const __half2* v1 = (const __half2*)&u1;
        const __half2* v2 = (const __half2*)&u2;
        const __half2* v3 = (const __half2*)&u3;
#pragma unroll
        for (int i = 0; i < 4; ++i) {
            float2 f0 = __half22float2(v0[i]);
            float2 f1 = __half22float2(v1[i]);
            float2 f2 = __half22float2(v2[i]);
            float2 f3 = __half22float2(v3[i]);
            acc[2 * i]     = fmaf(w0, f0.x, fmaf(w1, f1.x, fmaf(w2, f2.x, fmaf(w3, f3.x, acc[2 * i]))));
            acc[2 * i + 1] = fmaf(w0, f0.y, fmaf(w1, f1.y, fmaf(w2, f2.y, fmaf(w3, f3.y, acc[2 * i + 1]))));
        }
    }

    __half2 h0 = __floats2half2_rn(fmaxf(acc[0], 0.f), fmaxf(acc[1], 0.f));
    __half2 h1 = __floats2half2_rn(fmaxf(acc[2], 0.f), fmaxf(acc[3], 0.f));
    __half2 h2 = __floats2half2_rn(fmaxf(acc[4], 0.f), fmaxf(acc[5], 0.f));
    __half2 h3 = __floats2half2_rn(fmaxf(acc[6], 0.f), fmaxf(acc[7], 0.f));
    __half2* Ap = (__half2*)(g_agg + (size_t)v * 256 + lane * 8);
    Ap[0] = h0; Ap[1] = h1; Ap[2] = h2; Ap[3] = h3;
}

// ---------------- side stream / events / attrs (created once, before any capture) ----------------
struct Aux {
    cudaStream_t s2;
    cudaEvent_t evFork, evW, evConv, evCSR, evV;
    Aux() {
        cudaStreamCreateWithFlags(&s2, cudaStreamNonBlocking);
        cudaEventCreateWithFlags(&evFork, cudaEventDisableTiming);
        cudaEventCreateWithFlags(&evW,    cudaEventDisableTiming);
        cudaEventCreateWithFlags(&evConv, cudaEventDisableTiming);
        cudaEventCreateWithFlags(&evCSR,  cudaEventDisableTiming);
        cudaEventCreateWithFlags(&evV,    cudaEventDisableTiming);
        cudaFuncSetAttribute(mlp_fused,
                             cudaFuncAttributeMaxDynamicSharedMemorySize, MLP_SMEM);
    }
};
static Aux g_aux;

// ---------------- launch ----------------
extern "C" void kernel_launch(void* const* d_in, const int* in_sizes, int n_in,
                              void* d_out, int out_size)
{
    const float* x    = (const float*)d_in[0];
    const int*   ei   = (const int*)d_in[1];
    const float* Wk   = (const float*)d_in[2];
    const float* bk   = (const float*)d_in[3];
    const float* Wq   = (const float*)d_in[4];
    const float* bq   = (const float*)d_in[5];
    const float* Wv   = (const float*)d_in[6];
    const float* bv   = (const float*)d_in[7];
    const float* Wagg = (const float*)d_in[8];
    const float* bagg = (const float*)d_in[9];
    const float* Wff  = (const float*)d_in[10];
    const float* bff  = (const float*)d_in[11];
    float* out = (float*)d_out;

    const int n = in_sizes[0] / 256;
    const int m = in_sizes[1] / 2;
    const int* recv = ei;
    const int* send = ei + m;

    __half *xhp, *Qp, *Kp, *Vp, *aggp, *WTp;
    cudaGetSymbolAddress((void**)&xhp,  g_xh);
    cudaGetSymbolAddress((void**)&Qp,   g_Q);
    cudaGetSymbolAddress((void**)&Kp,   g_K);
    cudaGetSymbolAddress((void**)&Vp,   g_V);
    cudaGetSymbolAddress((void**)&aggp, g_agg);
    cudaGetSymbolAddress((void**)&WTp,  g_WT);

    cudaStream_t s2 = g_aux.s2;
    const int gx = (n + 127) / 128;

    // fork side branch
    cudaEventRecord(g_aux.evFork, 0);
    cudaStreamWaitEvent(s2, g_aux.evFork, 0);

    // side: weight conversion (evW gates QK on main), then CSR build
    conv_w<<<dim3(8, 8, 5), dim3(32, 32), 0, s2>>>(Wq, Wk, Wv, Wagg, Wff);
    cudaEventRecord(g_aux.evW, s2);
    init_kernel<<<(n + 255) / 256, 256, 0, s2>>>(n);
    hist_kernel<<<(m + 255) / 256, 256, 0, s2>>>(recv, m);
    scan_p1<<<SCAN_NB, SCAN_NT, 0, s2>>>(n);
    scan_p2<<<1, SCAN_NB, 0, s2>>>();
    scan_p3<<<SCAN_NB, SCAN_NT, 0, s2>>>(n, m);
    permute_kernel<<<(m + 255) / 256, 256, 0, s2>>>(recv, send, m);
    cudaEventRecord(g_aux.evCSR, s2);

    // main: x conversion
    conv_x<<<(n * 64 + 255) / 256, 256>>>(x, n * 64);
    cudaEventRecord(g_aux.evConv, 0);

    // side: V projection
    cudaStreamWaitEvent(s2, g_aux.evConv, 0);
    GemmSet sv = {WTp + 2 * 65536, bv, Vp};
    gemm_h<true><<<dim3(gx, 2, 1), 256, 0, s2>>>(xhp, sv, sv, sv, n);
    cudaEventRecord(g_aux.evV, s2);

    // main: Q/K projections (wait only for the weight conversion)
    cudaStreamWaitEvent(0, g_aux.evW, 0);
    GemmSet sq = {WTp,         bq, Qp};
    GemmSet sk = {WTp + 65536, bk, Kp};
    gemm_h<true><<<dim3(gx, 2, 2), 256>>>(xhp, sq, sk, sk, n);

    // join CSR, then node-centric edge logits
    cudaStreamWaitEvent(0, g_aux.evCSR, 0);
    node_qk<<<(n + 7) / 8, 256>>>(n);

    // join V, then aggregation
    cudaStreamWaitEvent(0, g_aux.evV, 0);
    node_msg<<<(n + 7) / 8, 256>>>(n);

    // fused MLP tail
    mlp_fused<<<gx, 256, MLP_SMEM>>>(aggp, WTp + 3 * 65536, bagg,
                                     WTp + 4 * 65536, bff, x, out, n);
}

// round 14
// speedup vs baseline: 1.0221x; 1.0086x over previous
#include <cuda_runtime.h>
#include <cuda_fp16.h>
#include <math.h>

#define NMAX 50000
#define MMAX 800000
#define DD 256

// ---------------- scratch (static device globals; no allocation) ----------------
__device__ __align__(16) __half g_xh[(size_t)NMAX * DD];   // x in fp16 (GEMM A)
__device__ __align__(16) __half g_Q[(size_t)NMAX * DD];
__device__ __align__(16) __half g_K[(size_t)NMAX * DD];
__device__ __align__(16) __half g_V[(size_t)NMAX * DD];
__device__ __align__(16) __half g_agg[(size_t)NMAX * DD];  // relu'd messages (fp16)
__device__ __align__(16) __half g_WT[5 * 65536];           // weights fp16, [n][k]
__device__ __align__(16) __half g_att[(size_t)MMAX * 8];   // qk logits fp16 (CSR order)
__device__ int g_hist[NMAX];
__device__ int g_cursor[NMAX];
__device__ int g_rowoff[NMAX + 1];
__device__ int g_send_s[MMAX];
__device__ int g_bsum[64];
__device__ int g_maxbits;

__device__ __forceinline__ int f2ord(float f) {
    int b = __float_as_int(f);
    return b >= 0 ? b : (b ^ 0x7FFFFFFF);
}
__device__ __forceinline__ float ord2f(int b) {
    return __int_as_float(b >= 0 ? b : (b ^ 0x7FFFFFFF));
}

__device__ __forceinline__ void mma_f16(float* c, unsigned a0, unsigned a1,
                                        unsigned a2, unsigned a3,
                                        unsigned b0, unsigned b1) {
    asm volatile(
        "mma.sync.aligned.m16n8k16.row.col.f32.f16.f16.f32 "
        "{%0,%1,%2,%3}, {%4,%5,%6,%7}, {%8,%9}, {%0,%1,%2,%3};"
        : "+f"(c[0]), "+f"(c[1]), "+f"(c[2]), "+f"(c[3])
        : "r"(a0), "r"(a1), "r"(a2), "r"(a3), "r"(b0), "r"(b1));
}

__device__ __forceinline__ void ldsm_x4(unsigned& r0, unsigned& r1,
                                        unsigned& r2, unsigned& r3, const __half* p) {
    unsigned a = (unsigned)__cvta_generic_to_shared(p);
    asm volatile("ldmatrix.sync.aligned.m8n8.x4.shared.b16 {%0,%1,%2,%3}, [%4];"
                 : "=r"(r0), "=r"(r1), "=r"(r2), "=r"(r3) : "r"(a));
}

__device__ __forceinline__ void cp_async16(void* smem, const void* gmem) {
    unsigned sa = (unsigned)__cvta_generic_to_shared(smem);
    asm volatile("cp.async.cg.shared.global [%0], [%1], 16;" :: "r"(sa), "l"(gmem));
}
__device__ __forceinline__ void cp_async16_pred(void* smem, const void* gmem, bool p) {
    unsigned sa = (unsigned)__cvta_generic_to_shared(smem);
    int sz = p ? 16 : 0;
    asm volatile("cp.async.cg.shared.global [%0], [%1], 16, %2;"
                 :: "r"(sa), "l"(gmem), "r"(sz));
}
__device__ __forceinline__ void cp_commit() {
    asm volatile("cp.async.commit_group;");
}
template<int N>
__device__ __forceinline__ void cp_wait() {
    asm volatile("cp.async.wait_group %0;" :: "n"(N));
}

// ---------------- CSR build ----------------
__global__ void init_kernel(int n) {
    int i = blockIdx.x * blockDim.x + threadIdx.x;
    if (i < n) g_hist[i] = 0;
    if (i == 0) g_maxbits = 0x80000000;
}

__global__ void hist_kernel(const int* __restrict__ recv, int m) {
    int i = blockIdx.x * blockDim.x + threadIdx.x;
    if (i < m) atomicAdd(&g_hist[recv[i]], 1);
}

#define SCAN_NB 64
#define SCAN_NT 256

__global__ __launch_bounds__(SCAN_NT)
void scan_p1(int n) {
    __shared__ int sh[SCAN_NT];
    const int chunk = (n + SCAN_NB * SCAN_NT - 1) / (SCAN_NB * SCAN_NT);
    const int gid = blockIdx.x * SCAN_NT + threadIdx.x;
    const int base = gid * chunk;
    const int lim = min(base + chunk, n);
    int s = 0;
    for (int i = base; i < lim; ++i) s += g_hist[i];
    sh[threadIdx.x] = s;
    __syncthreads();
    for (int off = SCAN_NT / 2; off; off >>= 1) {
        if (threadIdx.x < off) sh[threadIdx.x] += sh[threadIdx.x + off];
        __syncthreads();
    }
    if (threadIdx.x == 0) g_bsum[blockIdx.x] = sh[0];
}

__global__ __launch_bounds__(SCAN_NB)
void scan_p2() {
    __shared__ int sh[SCAN_NB];
    const int t = threadIdx.x;
    int v = g_bsum[t];
    sh[t] = v;
    __syncthreads();
    for (int off = 1; off < SCAN_NB; off <<= 1) {
        int u = (t >= off) ? sh[t - off] : 0;
        __syncthreads();
        sh[t] += u;
        __syncthreads();
    }
    g_bsum[t] = sh[t] - v;
}

__global__ __launch_bounds__(SCAN_NT)
void scan_p3(int n, int m) {
    __shared__ int sh[SCAN_NT];
    const int chunk = (n + SCAN_NB * SCAN_NT - 1) / (SCAN_NB * SCAN_NT);
    const int gid = blockIdx.x * SCAN_NT + threadIdx.x;
    const int base = gid * chunk;
    const int lim = min(base + chunk, n);
    int s = 0;
    for (int i = base; i < lim; ++i) s += g_hist[i];
    sh[threadIdx.x] = s;
    __syncthreads();
    for (int off = 1; off < SCAN_NT; off <<= 1) {
        int u = (threadIdx.x >= off) ? sh[threadIdx.x - off] : 0;
        __syncthreads();
        sh[threadIdx.x] += u;
        __syncthreads();
    }
    int run = g_bsum[blockIdx.x] + sh[threadIdx.x] - s;
    for (int i = base; i < lim; ++i) {
        int c = g_hist[i];
        g_rowoff[i] = run;
        g_cursor[i] = run;
        run += c;
    }
    if (gid == 0) g_rowoff[n] = m;
}

__global__ void permute_kernel(const int* __restrict__ recv,
                               const int* __restrict__ send, int m) {
    int e = blockIdx.x * blockDim.x + threadIdx.x;
    if (e >= m) return;
    int r = recv[e];
    int pos = atomicAdd(&g_cursor[r], 1);
    g_send_s[pos] = send[e];
}

// ---------------- conversions ----------------
__global__ void conv_x(const float* __restrict__ x, int n4) {
    int i = blockIdx.x * blockDim.x + threadIdx.x;
    if (i >= n4) return;
    float4 v = ((const float4*)x)[i];
    ((__half2*)g_xh)[2 * i]     = __floats2half2_rn(v.x, v.y);
    ((__half2*)g_xh)[2 * i + 1] = __floats2half2_rn(v.z, v.w);
}

__global__ void conv_w(const float* w0, const float* w1, const float* w2,
                       const float* w3, const float* w4) {
    __shared__ float t[32][33];
    const float* W = (blockIdx.z == 0) ? w0 : (blockIdx.z == 1) ? w1 :
                     (blockIdx.z == 2) ? w2 : (blockIdx.z == 3) ? w3 : w4;
    int k0 = blockIdx.y * 32, n0 = blockIdx.x * 32;
    t[threadIdx.y][threadIdx.x] = W[(size_t)(k0 + threadIdx.y) * 256 + n0 + threadIdx.x];
    __syncthreads();
    g_WT[(size_t)blockIdx.z * 65536 + (size_t)(n0 + threadIdx.y) * 256 + k0 + threadIdx.x] =
        __float2half_rn(t[threadIdx.x][threadIdx.y]);
}

// ---------------- fp16 tensor-core GEMM, cp.async + ldmatrix ----------------
struct GemmSet { const __half* WT; const float* b; void* C; };

#define TS 40   // pipeline smem stride (halves)
#define HS 264  // h1 smem stride (halves)

template<bool OUT_HALF>
__global__ __launch_bounds__(256)
void gemm_h(const __half* __restrict__ A,
            GemmSet s0, GemmSet s1, GemmSet s2, int nrows)
{
    __shared__ __align__(16) __half As[2][128 * TS];
    __shared__ __align__(16) __half Ws[2][128 * TS];

    const GemmSet gs = (blockIdx.z == 0) ? s0 : (blockIdx.z == 1) ? s1 : s2;
    const __half* __restrict__ WT  = gs.WT;
    const float* __restrict__ bias = gs.b;

    const int tid  = threadIdx.x;
    const int lane = tid & 31;
    const int warp = tid >> 5;
    const int wm   = warp >> 2;
    const int wn   = warp & 3;
    const int m0   = blockIdx.x * 128;
    const int n0   = blockIdx.y * 128;
    const int g    = lane >> 2;
    const int t2   = (lane & 3) * 2;

    const int arow = ((lane >> 3) & 1) * 8 + (lane & 7);
    const int acol = (lane >> 4) * 8;
    const int brow = (lane >> 4) * 8 + (lane & 7);
    const int bcol = ((lane >> 3) & 1) * 8;

    const int lrow = tid >> 2;
    const int lkv  = tid & 3;

    float acc[4][4][4];
#pragma unroll
    for (int i = 0; i < 4; i++)
#pragma unroll
        for (int j = 0; j < 4; j++)
#pragma unroll
            for (int k = 0; k < 4; k++) acc[i][j][k] = 0.f;

    auto load_tiles = [&](int st, int k0) {
#pragma unroll
        for (int it = 0; it < 2; ++it) {
            int row = it * 64 + lrow;
            int gm  = m0 + row;
            bool ok = gm < nrows;
            const __half* src = A + (size_t)(ok ? gm : 0) * 256 + k0 + lkv * 8;
            cp_async16_pred(&As[st][row * TS + lkv * 8], src, ok);
        }
#pragma unroll
        for (int it = 0; it < 2; ++it) {
            int row = it * 64 + lrow;
            cp_async16(&Ws[st][row * TS + lkv * 8],
                       WT + (size_t)(n0 + row) * 256 + k0 + lkv * 8);
        }
    };

    load_tiles(0, 0);
    cp_commit();

#pragma unroll 1
    for (int kt = 0; kt < 8; ++kt) {
        const int cur = kt & 1;
        if (kt < 7) {
            load_tiles(cur ^ 1, (kt + 1) * 32);
            cp_commit();
            cp_wait<1>();
        } else {
            cp_wait<0>();
        }
        __syncthreads();

        const __half* Ab = As[cur];
        const __half* Wb = Ws[cur];
#pragma unroll
        for (int ks = 0; ks < 2; ++ks) {
            const int kk = ks * 16;
            unsigned af[4][4];
#pragma unroll
            for (int mt = 0; mt < 4; ++mt)
                ldsm_x4(af[mt][0], af[mt][1], af[mt][2], af[mt][3],
                        &Ab[(wm * 64 + mt * 16 + arow) * TS + kk + acol]);
            unsigned bf[4][2];
#pragma unroll
            for (int ntp = 0; ntp < 2; ++ntp)
                ldsm_x4(bf[2 * ntp][0], bf[2 * ntp][1],
                        bf[2 * ntp + 1][0], bf[2 * ntp + 1][1],
                        &Wb[(wn * 32 + ntp * 16 + brow) * TS + kk + bcol]);
#pragma unroll
            for (int mt = 0; mt < 4; ++mt)
#pragma unroll
                for (int nt = 0; nt < 4; ++nt)
                    mma_f16(acc[mt][nt], af[mt][0], af[mt][1], af[mt][2], af[mt][3],
                            bf[nt][0], bf[nt][1]);
        }
        __syncthreads();
    }

#pragma unroll
    for (int mt = 0; mt < 4; ++mt) {
#pragma unroll
        for (int nt = 0; nt < 4; ++nt) {
            int c  = n0 + wn * 32 + nt * 8 + t2;
            float2 b = *(const float2*)(bias + c);
            int r0 = m0 + wm * 64 + mt * 16 + g;
#pragma unroll
            for (int h = 0; h < 2; ++h) {
                int gm = r0 + h * 8;
                if (gm < nrows) {
                    float2 o;
                    o.x = acc[mt][nt][h * 2 + 0] + b.x;
                    o.y = acc[mt][nt][h * 2 + 1] + b.y;
                    if (OUT_HALF) {
                        *(__half2*)((__half*)gs.C + (size_t)gm * 256 + c) =
                            __float22half2_rn(o);
                    } else {
                        *(float2*)((float*)gs.C + (size_t)gm * 256 + c) = o;
                    }
                }
            }
        }
    }
}

// ---------------- fused MLP tail: out = relu(relu(agg@Wa+ba)@Wf+bf) + x ----------------
__global__ __launch_bounds__(256)
void mlp_fused(const __half* __restrict__ A,
               const __half* __restrict__ WTa, const float* __restrict__ ba,
               const __half* __restrict__ WTf, const float* __restrict__ bf,
               const float* __restrict__ x, float* __restrict__ out, int nrows)
{
    extern __shared__ __align__(16) char dyn[];
    __half* As = (__half*)dyn;                 // [2][128*TS]
    __half* Ws = As + 2 * 128 * TS;            // [2][128*TS]
    __half* H1 = Ws + 2 * 128 * TS;            // [128][HS]

    const int tid  = threadIdx.x;
    const int lane = tid & 31;
    const int warp = tid >> 5;
    const int wm   = warp >> 2;
    const int wn   = warp & 3;
    const int m0   = blockIdx.x * 128;
    const int g    = lane >> 2;
    const int t2   = (lane & 3) * 2;
    const int arow = ((lane >> 3) & 1) * 8 + (lane & 7);
    const int acol = (lane >> 4) * 8;
    const int brow = (lane >> 4) * 8 + (lane & 7);
    const int bcol = ((lane >> 3) & 1) * 8;
    const int lrow = tid >> 2;
    const int lkv  = tid & 3;

    // ---- stage 1: h1 = relu(A @ Wa + ba) ----
#pragma unroll 1
    for (int nh = 0; nh < 2; ++nh) {
        const int n0 = nh * 128;

        float acc[4][4][4];
#pragma unroll
        for (int i = 0; i < 4; i++)
#pragma unroll
            for (int j = 0; j < 4; j++)
#pragma unroll
                for (int k = 0; k < 4; k++) acc[i][j][k] = 0.f;

        auto load1 = [&](int st, int k0) {
#pragma unroll
            for (int it = 0; it < 2; ++it) {
                int row = it * 64 + lrow;
                int gm  = m0 + row;
                bool ok = gm < nrows;
                const __half* src = A + (size_t)(ok ? gm : 0) * 256 + k0 + lkv * 8;
                cp_async16_pred(&As[st * 128 * TS + row * TS + lkv * 8], src, ok);
            }
#pragma unroll
            for (int it = 0; it < 2; ++it) {
                int row = it * 64 + lrow;
                cp_async16(&Ws[st * 128 * TS + row * TS + lkv * 8],
                           WTa + (size_t)(n0 + row) * 256 + k0 + lkv * 8);
            }
        };
        load1(0, 0);
        cp_commit();

#pragma unroll 1
        for (int kt = 0; kt < 8; ++kt) {
            const int cur = kt & 1;
            if (kt < 7) { load1(cur ^ 1, (kt + 1) * 32); cp_commit(); cp_wait<1>(); }
            else        { cp_wait<0>(); }
            __syncthreads();

            const __half* Ab = As + cur * 128 * TS;
            const __half* Wb = Ws + cur * 128 * TS;
#pragma unroll
            for (int ks = 0; ks < 2; ++ks) {
                const int kk = ks * 16;
                unsigned af[4][4];
#pragma unroll
                for (int mt = 0; mt < 4; ++mt)
                    ldsm_x4(af[mt][0], af[mt][1], af[mt][2], af[mt][3],
                            &Ab[(wm * 64 + mt * 16 + arow) * TS + kk + acol]);
                unsigned bfr[4][2];
#pragma unroll
                for (int ntp = 0; ntp < 2; ++ntp)
                    ldsm_x4(bfr[2 * ntp][0], bfr[2 * ntp][1],
                            bfr[2 * ntp + 1][0], bfr[2 * ntp + 1][1],
                            &Wb[(wn * 32 + ntp * 16 + brow) * TS + kk + bcol]);
#pragma unroll
                for (int mt = 0; mt < 4; ++mt)
#pragma unroll
                    for (int nt = 0; nt < 4; ++nt)
                        mma_f16(acc[mt][nt], af[mt][0], af[mt][1], af[mt][2], af[mt][3],
                                bfr[nt][0], bfr[nt][1]);
            }
            __syncthreads();
        }

#pragma unroll
        for (int mt = 0; mt < 4; ++mt) {
#pragma unroll
            for (int nt = 0; nt < 4; ++nt) {
                int cl = wn * 32 + nt * 8 + t2;
                float2 b = *(const float2*)(ba + n0 + cl);
                int rl = wm * 64 + mt * 16 + g;
#pragma unroll
                for (int h = 0; h < 2; ++h) {
                    float2 o;
                    o.x = fmaxf(acc[mt][nt][h * 2 + 0] + b.x, 0.f);
                    o.y = fmaxf(acc[mt][nt][h * 2 + 1] + b.y, 0.f);
                    *(__half2*)(&H1[(rl + h * 8) * HS + n0 + cl]) = __float22half2_rn(o);
                }
            }
        }
        __syncthreads();
    }

    // ---- stage 2: out = relu(h1 @ Wf + bf) + x ----
#pragma unroll 1
    for (int nh = 0; nh < 2; ++nh) {
        const int n0 = nh * 128;

        float acc[4][4][4];
#pragma unroll
        for (int i = 0; i < 4; i++)
#pragma unroll
            for (int j = 0; j < 4; j++)
#pragma unroll
                for (int k = 0; k < 4; k++) acc[i][j][k] = 0.f;

        auto load2 = [&](int st, int k0) {
#pragma unroll
            for (int it = 0; it < 2; ++it) {
                int row = it * 64 + lrow;
                cp_async16(&Ws[st * 128 * TS + row * TS + lkv * 8],
                           WTf + (size_t)(n0 + row) * 256 + k0 + lkv * 8);
            }
        };
        load2(0, 0);
        cp_commit();

#pragma unroll 1
        for (int kt = 0; kt < 8; ++kt) {
            const int cur = kt & 1;
            if (kt < 7) { load2(cur ^ 1, (kt + 1) * 32); cp_commit(); cp_wait<1>(); }
            else        { cp_wait<0>(); }
            __syncthreads();

            const int k0 = kt * 32;
            const __half* Wb = Ws + cur * 128 * TS;
#pragma unroll
            for (int ks = 0; ks < 2; ++ks) {
                const int kk = ks * 16;
                unsigned af[4][4];
#pragma unroll
                for (int mt = 0; mt < 4; ++mt)
                    ldsm_x4(af[mt][0], af[mt][1], af[mt][2], af[mt][3],
                            &H1[(wm * 64 + mt * 16 + arow) * HS + k0 + kk + acol]);
                unsigned bfr[4][2];
#pragma unroll
                for (int ntp = 0; ntp < 2; ++ntp)
                    ldsm_x4(bfr[2 * ntp][0], bfr[2 * ntp][1],
                            bfr[2 * ntp + 1][0], bfr[2 * ntp + 1][1],
                            &Wb[(wn * 32 + ntp * 16 + brow) * TS + kk + bcol]);
#pragma unroll
                for (int mt = 0; mt < 4; ++mt)
#pragma unroll
                    for (int nt = 0; nt < 4; ++nt)
                        mma_f16(acc[mt][nt], af[mt][0], af[mt][1], af[mt][2], af[mt][3],
                                bfr[nt][0], bfr[nt][1]);
            }
            __syncthreads();
        }

#pragma unroll
        for (int mt = 0; mt < 4; ++mt) {
#pragma unroll
            for (int nt = 0; nt < 4; ++nt) {
                int c  = n0 + wn * 32 + nt * 8 + t2;
                float2 b = *(const float2*)(bf + c);
                int r0 = m0 + wm * 64 + mt * 16 + g;
#pragma unroll
                for (int h = 0; h < 2; ++h) {
                    int gm = r0 + h * 8;
                    if (gm < nrows) {
                        float2 r = *(const float2*)(x + (size_t)gm * 256 + c);
                        float2 o;
                        o.x = fmaxf(acc[mt][nt][h * 2 + 0] + b.x, 0.f) + r.x;
                        o.y = fmaxf(acc[mt][nt][h * 2 + 1] + b.y, 0.f) + r.y;
                        *(float2*)(out + (size_t)gm * 256 + c) = o;
                    }
                }
            }
        }
        __syncthreads();
    }
}

#define MLP_SMEM (2 * 128 * TS * 2 * 2 + 128 * HS * 2)  // 108544 B

// ---------------- node qk: warp per node; Q in registers, 4 K gathers in flight ----------------
__global__ __launch_bounds__(256)
void node_qk(int n)
{
    __shared__ int smax;
    if (threadIdx.x == 0) smax = 0x80000000;
    __syncthreads();

    const int warp = threadIdx.x >> 5;
    const int lane = threadIdx.x & 31;
    const int v = blockIdx.x * 8 + warp;
    const int h = lane >> 2;

    float mx = -1e30f;
    if (v < n) {
        const int off = g_rowoff[v];
        const int end = g_rowoff[v + 1];

        uint4 qu = ((const uint4*)(g_Q + (size_t)v * 256))[lane];
        const __half2* qh = (const __half2*)&qu;
        float qf[8];
#pragma unroll
        for (int i = 0; i < 4; ++i) {
            float2 f = __half22float2(qh[i]);
            qf[2 * i] = f.x; qf[2 * i + 1] = f.y;
        }

        for (int e = off; e < end; e += 4) {
            const int cnt = end - e;
            const int s0 = g_send_s[e];
            const int s1 = cnt > 1 ? g_send_s[e + 1] : s0;
            const int s2 = cnt > 2 ? g_send_s[e + 2] : s0;
            const int s3 = cnt > 3 ? g_send_s[e + 3] : s0;
            uint4 k0 = ((const uint4*)(g_K + (size_t)s0 * 256))[lane];
            uint4 k1 = ((const uint4*)(g_K + (size_t)s1 * 256))[lane];
            uint4 k2 = ((const uint4*)(g_K + (size_t)s2 * 256))[lane];
            uint4 k3 = ((const uint4*)(g_K + (size_t)s3 * 256))[lane];
            const __half2* ka = (const __half2*)&k0;
            const __half2* kb = (const __half2*)&k1;
            const __half2* kc = (const __half2*)&k2;
            const __half2* kd = (const __half2*)&k3;
            float d0 = 0.f, d1 = 0.f, d2 = 0.f, d3 = 0.f;
#pragma unroll
            for (int i = 0; i < 4; ++i) {
                float2 fa = __half22float2(ka[i]);
                float2 fb = __half22float2(kb[i]);
                float2 fc = __half22float2(kc[i]);
                float2 fd = __half22float2(kd[i]);
                d0 = fmaf(qf[2 * i], fa.x, d0); d0 = fmaf(qf[2 * i + 1], fa.y, d0);
                d1 = fmaf(qf[2 * i], fb.x, d1); d1 = fmaf(qf[2 * i + 1], fb.y, d1);
                d2 = fmaf(qf[2 * i], fc.x, d2); d2 = fmaf(qf[2 * i + 1], fc.y, d2);
                d3 = fmaf(qf[2 * i], fd.x, d3); d3 = fmaf(qf[2 * i + 1], fd.y, d3);
            }
            d0 += __shfl_xor_sync(0xffffffffu, d0, 1);
            d0 += __shfl_xor_sync(0xffffffffu, d0, 2);
            d1 += __shfl_xor_sync(0xffffffffu, d1, 1);
            d1 += __shfl_xor_sync(0xffffffffu, d1, 2);
            d2 += __shfl_xor_sync(0xffffffffu, d2, 1);
            d2 += __shfl_xor_sync(0xffffffffu, d2, 2);
            d3 += __shfl_xor_sync(0xffffffffu, d3, 1);
            d3 += __shfl_xor_sync(0xffffffffu, d3, 2);
            if ((lane & 3) == 0) {
                g_att[(size_t)e * 8 + h] = __float2half_rn(d0);
                mx = fmaxf(mx, d0);
                if (cnt > 1) { g_att[(size_t)(e + 1) * 8 + h] = __float2half_rn(d1); mx = fmaxf(mx, d1); }
                if (cnt > 2) { g_att[(size_t)(e + 2) * 8 + h] = __float2half_rn(d2); mx = fmaxf(mx, d2); }
                if (cnt > 3) { g_att[(size_t)(e + 3) * 8 + h] = __float2half_rn(d3); mx = fmaxf(mx, d3); }
            }
        }
    }
#pragma unroll
    for (int off = 16; off; off >>= 1)
        mx = fmaxf(mx, __shfl_xor_sync(0xffffffffu, mx, off));
    if (lane == 0) atomicMax(&smax, f2ord(mx));
    __syncthreads();
    if (threadIdx.x == 0) atomicMax(&g_maxbits, smax);
}

// ---------------- single-pass softmax-aggregation: warp per node ----------------
// acc = sum exp(l)*V ; dsum = sum exp(l) ; out = acc/(dsum*sqrt32), relu, fp16.
__global__ __launch_bounds__(256)
void node_msg(int n)
{
    __shared__ float sscale;
    if (threadIdx.x == 0) sscale = 3.0f / ord2f(g_maxbits);
    __syncthreads();
    const float scale = sscale;

    const int warp = threadIdx.x >> 5;
    const int lane = threadIdx.x & 31;
    const int v = blockIdx.x * 8 + warp;
    if (v >= n) return;

    const int off = g_rowoff[v];
    const int end = g_rowoff[v + 1];
    const int h = lane >> 2;

    float dsum = 0.f;
    float acc[8] = {0.f, 0.f, 0.f, 0.f, 0.f, 0.f, 0.f, 0.f};

    for (int e = off; e < end; e += 4) {
        const int cnt = end - e;
        const int s0 = g_send_s[e];
        const int s1 = cnt > 1 ? g_send_s[e + 1] : s0;
        const int s2 = cnt > 2 ? g_send_s[e + 2] : s0;
        const int s3 = cnt > 3 ? g_send_s[e + 3] : s0;
        uint4 u0 = ((const uint4*)(g_V + (size_t)s0 * 256))[lane];
        uint4 u1 = ((const uint4*)(g_V + (size_t)s1 * 256))[lane];
        uint4 u2 = ((const uint4*)(g_V + (size_t)s2 * 256))[lane];
        uint4 u3 = ((const uint4*)(g_V + (size_t)s3 * 256))[lane];
        float w0 = __expf(__half2float(g_att[(size_t)e * 8 + h]) * scale);
        float w1 = cnt > 1 ? __expf(__half2float(g_att[(size_t)(e + 1) * 8 + h]) * scale) : 0.f;
        float w2 = cnt > 2 ? __expf(__half2float(g_att[(size_t)(e + 2) * 8 + h]) * scale) : 0.f;
        float w3 = cnt > 3 ? __expf(__half2float(g_att[(size_t)(e + 3) * 8 + h]) * scale) : 0.f;
        dsum += (w0 + w1) + (w2 + w3);
        const __half2* v0 = (const __half2*)&u0;
        const __half2* v1 = (const __half2*)&u1;
        const __half2* v2 = (const __half2*)&u2;
        const __half2* v3 = (const __half2*)&u3;
#pragma unroll
        for (int i = 0; i < 4; ++i) {
            float2 f0 = __half22float2(v0[i]);
            float2 f1 = __half22float2(v1[i]);
            float2 f2 = __half22float2(v2[i]);
            float2 f3 = __half22float2(v3[i]);
            acc[2 * i]     = fmaf(w0, f0.x, fmaf(w1, f1.x, fmaf(w2, f2.x, fmaf(w3, f3.x, acc[2 * i]))));
            acc[2 * i + 1] = fmaf(w0, f0.y, fmaf(w1, f1.y, fmaf(w2, f2.y, fmaf(w3, f3.y, acc[2 * i + 1]))));
        }
    }

    const float inv = (dsum > 0.f) ? 1.0f / (dsum * 5.656854249492381f) : 0.f;
#pragma unroll
    for (int i = 0; i < 8; ++i) acc[i] *= inv;

    __half2 h0 = __floats2half2_rn(fmaxf(acc[0], 0.f), fmaxf(acc[1], 0.f));
    __half2 h1 = __floats2half2_rn(fmaxf(acc[2], 0.f), fmaxf(acc[3], 0.f));
    __half2 h2 = __floats2half2_rn(fmaxf(acc[4], 0.f), fmaxf(acc[5], 0.f));
    __half2 h3 = __floats2half2_rn(fmaxf(acc[6], 0.f), fmaxf(acc[7], 0.f));
    __half2* Ap = (__half2*)(g_agg + (size_t)v * 256 + lane * 8);
    Ap[0] = h0; Ap[1] = h1; Ap[2] = h2; Ap[3] = h3;
}

// ---------------- side stream / events / attrs (created once, before any capture) ----------------
struct Aux {
    cudaStream_t s2;
    cudaEvent_t evFork, evW, evConv, evCSR, evV;
    Aux() {
        cudaStreamCreateWithFlags(&s2, cudaStreamNonBlocking);
        cudaEventCreateWithFlags(&evFork, cudaEventDisableTiming);
        cudaEventCreateWithFlags(&evW,    cudaEventDisableTiming);
        cudaEventCreateWithFlags(&evConv, cudaEventDisableTiming);
        cudaEventCreateWithFlags(&evCSR,  cudaEventDisableTiming);
        cudaEventCreateWithFlags(&evV,    cudaEventDisableTiming);
        cudaFuncSetAttribute(mlp_fused,
                             cudaFuncAttributeMaxDynamicSharedMemorySize, MLP_SMEM);
    }
};
static Aux g_aux;

// ---------------- launch ----------------
extern "C" void kernel_launch(void* const* d_in, const int* in_sizes, int n_in,
                              void* d_out, int out_size)
{
    const float* x    = (const float*)d_in[0];
    const int*   ei   = (const int*)d_in[1];
    const float* Wk   = (const float*)d_in[2];
    const float* bk   = (const float*)d_in[3];
    const float* Wq   = (const float*)d_in[4];
    const float* bq   = (const float*)d_in[5];
    const float* Wv   = (const float*)d_in[6];
    const float* bv   = (const float*)d_in[7];
    const float* Wagg = (const float*)d_in[8];
    const float* bagg = (const float*)d_in[9];
    const float* Wff  = (const float*)d_in[10];
    const float* bff  = (const float*)d_in[11];
    float* out = (float*)d_out;

    const int n = in_sizes[0] / 256;
    const int m = in_sizes[1] / 2;
    const int* recv = ei;
    const int* send = ei + m;

    __half *xhp, *Qp, *Kp, *Vp, *aggp, *WTp;
    cudaGetSymbolAddress((void**)&xhp,  g_xh);
    cudaGetSymbolAddress((void**)&Qp,   g_Q);
    cudaGetSymbolAddress((void**)&Kp,   g_K);
    cudaGetSymbolAddress((void**)&Vp,   g_V);
    cudaGetSymbolAddress((void**)&aggp, g_agg);
    cudaGetSymbolAddress((void**)&WTp,  g_WT);

    cudaStream_t s2 = g_aux.s2;
    const int gx = (n + 127) / 128;

    // fork side branch
    cudaEventRecord(g_aux.evFork, 0);
    cudaStreamWaitEvent(s2, g_aux.evFork, 0);

    // side: weight conversion (evW gates QK on main), then CSR build
    conv_w<<<dim3(8, 8, 5), dim3(32, 32), 0, s2>>>(Wq, Wk, Wv, Wagg, Wff);
    cudaEventRecord(g_aux.evW, s2);
    init_kernel<<<(n + 255) / 256, 256, 0, s2>>>(n);
    hist_kernel<<<(m + 255) / 256, 256, 0, s2>>>(recv, m);
    scan_p1<<<SCAN_NB, SCAN_NT, 0, s2>>>(n);
    scan_p2<<<1, SCAN_NB, 0, s2>>>();
    scan_p3<<<SCAN_NB, SCAN_NT, 0, s2>>>(n, m);
    permute_kernel<<<(m + 255) / 256, 256, 0, s2>>>(recv, send, m);
    cudaEventRecord(g_aux.evCSR, s2);

    // main: x conversion
    conv_x<<<(n * 64 + 255) / 256, 256>>>(x, n * 64);
    cudaEventRecord(g_aux.evConv, 0);

    // side: V projection
    cudaStreamWaitEvent(s2, g_aux.evConv, 0);
    GemmSet sv = {WTp + 2 * 65536, bv, Vp};
    gemm_h<true><<<dim3(gx, 2, 1), 256, 0, s2>>>(xhp, sv, sv, sv, n);
    cudaEventRecord(g_aux.evV, s2);

    // main: Q/K projections (wait only for the weight conversion)
    cudaStreamWaitEvent(0, g_aux.evW, 0);
    GemmSet sq = {WTp,         bq, Qp};
    GemmSet sk = {WTp + 65536, bk, Kp};
    gemm_h<true><<<dim3(gx, 2, 2), 256>>>(xhp, sq, sk, sk, n);

    // join CSR, then node-centric edge logits
    cudaStreamWaitEvent(0, g_aux.evCSR, 0);
    node_qk<<<(n + 7) / 8, 256>>>(n);

    // join V, then single-pass aggregation
    cudaStreamWaitEvent(0, g_aux.evV, 0);
    node_msg<<<(n + 7) / 8, 256>>>(n);

    // fused MLP tail
    mlp_fused<<<gx, 256, MLP_SMEM>>>(aggp, WTp + 3 * 65536, bagg,
                                     WTp + 4 * 65536, bff, x, out, n);
}